// round 1
// baseline (speedup 1.0000x reference)
#include <cuda_runtime.h>

#define NB 16      // batch
#define NS 512     // seq
#define NH 384     // hidden
#define NL 2000    // max_mel_len
#define NBINS 256
#define H4 (NH/4)  // 96 float4 per row

// scratch (no allocation allowed in kernel_launch)
__device__ int g_seg[NB * NL];
__device__ int g_pidx[NB];
__device__ int g_eidx[NB];

// One block per batch row, 512 threads (one per source token).
__global__ void __launch_bounds__(NS) prep_kernel(
    const float* __restrict__ log_duration,
    const float* __restrict__ pitch,
    const float* __restrict__ energy,
    float* __restrict__ out_tail, int write_tail)
{
    const int b   = blockIdx.x;
    const int tid = threadIdx.x;

    __shared__ int   sc[NS];
    __shared__ float red[NS];
    __shared__ int   s_pidx, s_eidx;

    // duration = max(round(exp(ld) - 1), 0)
    const float ld = log_duration[b * NS + tid];
    const int d = (int)fmaxf(rintf(expf(ld) - 1.0f), 0.0f);

    // inclusive scan over S=512 (Hillis-Steele)
    sc[tid] = d;
    __syncthreads();
    #pragma unroll
    for (int off = 1; off < NS; off <<= 1) {
        int v = (tid >= off) ? sc[tid - off] : 0;
        __syncthreads();
        sc[tid] += v;
        __syncthreads();
    }
    const int cum   = sc[tid];
    const int start = cum - d;
    const int total = sc[NS - 1];

    // pitch mean -> bin
    red[tid] = pitch[b * NS + tid];
    __syncthreads();
    #pragma unroll
    for (int off = NS / 2; off > 0; off >>= 1) {
        if (tid < off) red[tid] += red[tid + off];
        __syncthreads();
    }
    if (tid == 0) {
        int pi = (int)(red[0] * (1.0f / NS));
        s_pidx = min(max(pi, 0), NBINS - 1);
    }
    __syncthreads();

    // energy mean -> bin
    red[tid] = energy[b * NS + tid];
    __syncthreads();
    #pragma unroll
    for (int off = NS / 2; off > 0; off >>= 1) {
        if (tid < off) red[tid] += red[tid + off];
        __syncthreads();
    }
    if (tid == 0) {
        int ei = (int)(red[0] * (1.0f / NS));
        s_eidx = min(max(ei, 0), NBINS - 1);
    }

    // init segment map to -1, then scatter each token's interval
    for (int l = tid; l < NL; l += NS) g_seg[b * NL + l] = -1;
    __syncthreads();
    const int e = min(cum, NL);
    for (int l = start; l < e; ++l) g_seg[b * NL + l] = tid;

    if (tid == 0) {
        g_pidx[b] = s_pidx;
        g_eidx[b] = s_eidx;
        if (write_tail) out_tail[b] = (float)min(total, NL);
    }
}

// Flat float4 expand: out[b,l,:] = (seg>=0 ? enc[b,seg,:] : 0) + pemb + eemb
__global__ void __launch_bounds__(256) expand_kernel(
    const float4* __restrict__ enc,
    const float4* __restrict__ pemb,
    const float4* __restrict__ eemb,
    float4* __restrict__ out)
{
    const int idx = blockIdx.x * blockDim.x + threadIdx.x;
    if (idx >= NB * NL * H4) return;

    const int q  = idx % H4;
    const int bl = idx / H4;
    const int b  = bl / NL;

    const int s = g_seg[bl];
    const int pi = g_pidx[b];
    const int ei = g_eidx[b];

    float4 v = make_float4(0.f, 0.f, 0.f, 0.f);
    if (s >= 0) v = enc[(b * NS + s) * H4 + q];

    const float4 pe = pemb[pi * H4 + q];
    // match reference order: (enc + pemb) + eemb
    v.x += pe.x; v.y += pe.y; v.z += pe.z; v.w += pe.w;
    const float4 ee = eemb[ei * H4 + q];
    v.x += ee.x; v.y += ee.y; v.z += ee.z; v.w += ee.w;

    out[idx] = v;
}

extern "C" void kernel_launch(void* const* d_in, const int* in_sizes, int n_in,
                              void* d_out, int out_size)
{
    const float* enc   = (const float*)d_in[0];  // (B,S,H)
    const float* ldur  = (const float*)d_in[1];  // (B,S)
    const float* pitch = (const float*)d_in[2];  // (B,S)
    const float* energ = (const float*)d_in[3];  // (B,S)
    const float* pemb  = (const float*)d_in[4];  // (256,H)
    const float* eemb  = (const float*)d_in[5];  // (256,H)

    float* out = (float*)d_out;
    const int main_elems = NB * NL * NH;
    const int write_tail = (out_size >= main_elems + NB) ? 1 : 0;

    prep_kernel<<<NB, NS>>>(ldur, pitch, energ, out + main_elems, write_tail);

    const int total4 = NB * NL * H4;
    const int threads = 256;
    const int blocks = (total4 + threads - 1) / threads;
    expand_kernel<<<blocks, threads>>>(
        (const float4*)enc, (const float4*)pemb, (const float4*)eemb,
        (float4*)out);
}

// round 2
// speedup vs baseline: 1.2909x; 1.2909x over previous
#include <cuda_runtime.h>

#define NB 16      // batch
#define NS 512     // seq
#define NH 384     // hidden
#define NL 2000    // max_mel_len
#define NBINS 256
#define H4 (NH/4)  // 96 float4 per row

// scratch (no allocation allowed in kernel_launch)
__device__ int    g_seg[NB * NL];
__device__ float4 g_comb[NB * H4];   // pemb[pi_b] + eemb[ei_b]

// One block per batch row, 512 threads (one per source token).
__global__ void __launch_bounds__(NS) prep_kernel(
    const float* __restrict__ log_duration,
    const float* __restrict__ pitch,
    const float* __restrict__ energy,
    const float4* __restrict__ pemb,
    const float4* __restrict__ eemb,
    float* __restrict__ out_tail, int write_tail)
{
    const int b    = blockIdx.x;
    const int tid  = threadIdx.x;
    const int warp = tid >> 5;
    const int lane = tid & 31;

    __shared__ int   wsum[16];
    __shared__ float wred[16];
    __shared__ int   s_pidx, s_eidx;

    // duration = max(round(exp(ld) - 1), 0)
    const float ld = log_duration[b * NS + tid];
    const int d = (int)fmaxf(rintf(expf(ld) - 1.0f), 0.0f);

    // ---- inclusive scan over S=512: warp shfl scan + cross-warp ----
    int x = d;
    #pragma unroll
    for (int off = 1; off < 32; off <<= 1) {
        int y = __shfl_up_sync(0xffffffffu, x, off);
        if (lane >= off) x += y;
    }
    if (lane == 31) wsum[warp] = x;
    __syncthreads();
    if (warp == 0 && lane < 16) {
        int v = wsum[lane];
        #pragma unroll
        for (int off = 1; off < 16; off <<= 1) {
            int y = __shfl_up_sync(0x0000ffffu, v, off);
            if (lane >= off) v += y;
        }
        wsum[lane] = v;
    }
    __syncthreads();
    const int cum   = x + (warp ? wsum[warp - 1] : 0);
    const int start = cum - d;
    const int total = wsum[15];

    // ---- pitch / energy means via shfl reductions ----
    float p = pitch[b * NS + tid];
    float e = energy[b * NS + tid];
    #pragma unroll
    for (int off = 16; off > 0; off >>= 1) {
        p += __shfl_xor_sync(0xffffffffu, p, off);
        e += __shfl_xor_sync(0xffffffffu, e, off);
    }
    if (lane == 0) wred[warp] = p;
    __syncthreads();
    if (tid == 0) {
        float s = 0.f;
        #pragma unroll
        for (int i = 0; i < 16; i++) s += wred[i];
        s_pidx = min(max((int)(s * (1.0f / NS)), 0), NBINS - 1);
    }
    __syncthreads();
    if (lane == 0) wred[warp] = e;
    __syncthreads();
    if (tid == 0) {
        float s = 0.f;
        #pragma unroll
        for (int i = 0; i < 16; i++) s += wred[i];
        s_eidx = min(max((int)(s * (1.0f / NS)), 0), NBINS - 1);
        if (write_tail) out_tail[b] = (float)min(total, NL);
    }
    __syncthreads();

    // ---- combined embedding row: comb = pemb[pi] + eemb[ei] ----
    if (tid < H4) {
        float4 pv = pemb[s_pidx * H4 + tid];
        float4 ev = eemb[s_eidx * H4 + tid];
        pv.x += ev.x; pv.y += ev.y; pv.z += ev.z; pv.w += ev.w;
        g_comb[b * H4 + tid] = pv;
    }

    // ---- segment map: init -1, scatter each token's interval ----
    for (int l = tid; l < NL; l += NS) g_seg[b * NL + l] = -1;
    __syncthreads();
    const int end = min(cum, NL);
    for (int l = start; l < end; ++l) g_seg[b * NL + l] = tid;
}

// grid (NL/16, NB), block (96, 4). Each thread owns column q, handles 4 rows.
__global__ void __launch_bounds__(384) expand_kernel(
    const float4* __restrict__ enc,
    float4* __restrict__ out)
{
    const int q  = threadIdx.x;                 // 0..95
    const int b  = blockIdx.y;                  // 0..15
    const int l0 = blockIdx.x * 16 + threadIdx.y;

    const float4 c = g_comb[b * H4 + q];
    const float4* __restrict__ encb = enc + b * (NS * H4);
    float4* __restrict__ outb = out + b * (NL * H4);
    const int* __restrict__ segb = g_seg + b * NL;

    #pragma unroll
    for (int i = 0; i < 4; i++) {
        const int l = l0 + i * 4;
        const int s = segb[l];
        float4 v = c;
        if (s >= 0) {
            const float4 ev = __ldg(&encb[s * H4 + q]);
            v.x += ev.x; v.y += ev.y; v.z += ev.z; v.w += ev.w;
        }
        outb[l * H4 + q] = v;
    }
}

extern "C" void kernel_launch(void* const* d_in, const int* in_sizes, int n_in,
                              void* d_out, int out_size)
{
    const float* enc   = (const float*)d_in[0];  // (B,S,H)
    const float* ldur  = (const float*)d_in[1];  // (B,S)
    const float* pitch = (const float*)d_in[2];  // (B,S)
    const float* energ = (const float*)d_in[3];  // (B,S)
    const float* pemb  = (const float*)d_in[4];  // (256,H)
    const float* eemb  = (const float*)d_in[5];  // (256,H)

    float* out = (float*)d_out;
    const int main_elems = NB * NL * NH;
    const int write_tail = (out_size >= main_elems + NB) ? 1 : 0;

    prep_kernel<<<NB, NS>>>(ldur, pitch, energ,
                            (const float4*)pemb, (const float4*)eemb,
                            out + main_elems, write_tail);

    dim3 grid(NL / 16, NB);
    dim3 block(96, 4);
    expand_kernel<<<grid, block>>>((const float4*)enc, (float4*)out);
}